// round 1
// baseline (speedup 1.0000x reference)
#include <cuda_runtime.h>
#include <cuda_bf16.h>
#include <math.h>

// ---------------------------------------------------------------------------
// Model dims (compile-time)
// ---------------------------------------------------------------------------
#define BB 4
#define TT 2048
#define DD 256
#define HH 4
#define HD 64
#define LL 2
#define QQ 128          // MAX_BITS*2 out queries

// ---------------------------------------------------------------------------
// Scratch (device globals; no runtime allocation allowed)
// ---------------------------------------------------------------------------
__device__ float g_x  [BB*TT*DD];        // residual stream
__device__ float g_xn [BB*TT*DD];        // layernormed activations
__device__ float g_qkv[BB*TT*3*DD];      // qkv projections
__device__ float g_att[BB*TT*DD];        // attention output (b,t,h,hd)
__device__ float g_h  [BB*TT*4*DD];      // ffn hidden

// ---------------------------------------------------------------------------
// Reductions
// ---------------------------------------------------------------------------
__device__ __forceinline__ float blockReduceSum256(float v) {
    __shared__ float sh[8];
    int lane = threadIdx.x & 31, wid = threadIdx.x >> 5;
    #pragma unroll
    for (int o = 16; o; o >>= 1) v += __shfl_xor_sync(0xffffffffu, v, o);
    if (lane == 0) sh[wid] = v;
    __syncthreads();
    if (wid == 0) {
        float r = (lane < 8) ? sh[lane] : 0.f;
        #pragma unroll
        for (int o = 4; o; o >>= 1) r += __shfl_xor_sync(0xffffffffu, r, o);
        if (lane == 0) sh[0] = r;
    }
    __syncthreads();
    float r = sh[0];
    __syncthreads();
    return r;
}

__device__ __forceinline__ float blockReduceMax256(float v) {
    __shared__ float sh[8];
    int lane = threadIdx.x & 31, wid = threadIdx.x >> 5;
    #pragma unroll
    for (int o = 16; o; o >>= 1) v = fmaxf(v, __shfl_xor_sync(0xffffffffu, v, o));
    if (lane == 0) sh[wid] = v;
    __syncthreads();
    if (wid == 0) {
        float r = (lane < 8) ? sh[lane] : -1e30f;
        #pragma unroll
        for (int o = 4; o; o >>= 1) r = fmaxf(r, __shfl_xor_sync(0xffffffffu, r, o));
        if (lane == 0) sh[0] = r;
    }
    __syncthreads();
    float r = sh[0];
    __syncthreads();
    return r;
}

// ---------------------------------------------------------------------------
// Embedding lookup:  x[b,t,:] = embed[tokens[b,t], :]
// ---------------------------------------------------------------------------
__global__ void embed_kernel(const int* __restrict__ tokens,
                             const float* __restrict__ embed,
                             float* __restrict__ x) {
    int row = blockIdx.x;               // B*T rows
    int d   = threadIdx.x;              // 256
    int tok = tokens[row];
    x[(size_t)row * DD + d] = embed[(size_t)tok * DD + d];
}

// ---------------------------------------------------------------------------
// LayerNorm over D=256, one block per row
// ---------------------------------------------------------------------------
__global__ void ln_kernel(const float* __restrict__ x,
                          const float* __restrict__ w,
                          const float* __restrict__ b,
                          float* __restrict__ y) {
    int row = blockIdx.x;
    int d   = threadIdx.x;
    float v  = x[(size_t)row * DD + d];
    float mu = blockReduceSum256(v) * (1.f / DD);
    float dv = v - mu;
    float var = blockReduceSum256(dv * dv) * (1.f / DD);
    float r = rsqrtf(var + 1e-5f);
    y[(size_t)row * DD + d] = dv * r * w[d] + b[d];
}

// ---------------------------------------------------------------------------
// GEMM: C[M,N] = A[M,K] @ B[K,N] + bias, with epilogue variants
//   EPI 0: bias
//   EPI 1: bias + exact gelu
//   EPI 2: bias + accumulate into existing C (residual)
// Block tile 64x64, K-tile 16, 256 threads, 4x4 per thread.
// All dims are multiples of tile sizes here (M=8192; N in {256,768,1024};
// K in {256,1024}) so no bounds checks.
// ---------------------------------------------------------------------------
template <int EPI>
__global__ __launch_bounds__(256) void gemm_kernel(
    const float* __restrict__ A, const float* __restrict__ B,
    const float* __restrict__ bias, float* __restrict__ C,
    int M, int N, int K) {
    __shared__ float As[16][64];
    __shared__ float Bs[16][64];
    int tid = threadIdx.x;
    int bm = blockIdx.y * 64, bn = blockIdx.x * 64;

    int arow = tid >> 2, acol = (tid & 3) * 4;
    int brow = tid >> 4, bcol = (tid & 15) * 4;
    int ty = tid >> 4, tx = tid & 15;

    float acc[4][4] = {};

    for (int k0 = 0; k0 < K; k0 += 16) {
        float4 av = *(const float4*)(A + (size_t)(bm + arow) * K + k0 + acol);
        As[acol + 0][arow] = av.x;
        As[acol + 1][arow] = av.y;
        As[acol + 2][arow] = av.z;
        As[acol + 3][arow] = av.w;
        *(float4*)&Bs[brow][bcol] =
            *(const float4*)(B + (size_t)(k0 + brow) * N + bn + bcol);
        __syncthreads();
        #pragma unroll
        for (int kk = 0; kk < 16; kk++) {
            float4 a = *(const float4*)&As[kk][ty * 4];
            float4 bq = *(const float4*)&Bs[kk][tx * 4];
            float ar[4] = {a.x, a.y, a.z, a.w};
            float br[4] = {bq.x, bq.y, bq.z, bq.w};
            #pragma unroll
            for (int i = 0; i < 4; i++)
                #pragma unroll
                for (int j = 0; j < 4; j++)
                    acc[i][j] += ar[i] * br[j];
        }
        __syncthreads();
    }

    #pragma unroll
    for (int i = 0; i < 4; i++) {
        int r = bm + ty * 4 + i;
        #pragma unroll
        for (int j = 0; j < 4; j++) {
            int c = bn + tx * 4 + j;
            float v = acc[i][j] + bias[c];
            if (EPI == 1) v = 0.5f * v * (1.f + erff(v * 0.70710678118654752f));
            if (EPI == 2) v += C[(size_t)r * N + c];
            C[(size_t)r * N + c] = v;
        }
    }
}

// ---------------------------------------------------------------------------
// RoPE applied in-place to q and k parts of g_qkv.
// One thread per (row, part in {q,k}, head, pair d<32): 256 threads/row.
// ---------------------------------------------------------------------------
__global__ void rope_kernel(float* __restrict__ qkv) {
    int idx  = blockIdx.x * blockDim.x + threadIdx.x;
    int d    = idx & 31;
    int h    = (idx >> 5) & 3;
    int part = (idx >> 7) & 1;
    int row  = idx >> 8;           // b*T + t
    int t    = row & (TT - 1);
    float inv = powf(10000.f, -(float)d * (1.f / 32.f));
    float ang = (float)t * inv;
    float s, c;
    sincosf(ang, &s, &c);
    float* p = qkv + (size_t)row * (3 * DD) + part * DD + h * HD;
    float x0 = p[d], x1 = p[d + 32];
    p[d]      = x0 * c - x1 * s;
    p[d + 32] = x1 * c + x0 * s;
}

// ---------------------------------------------------------------------------
// Causal attention, flash-style online softmax. One warp per (b,h,t) row.
// ---------------------------------------------------------------------------
__global__ __launch_bounds__(128) void attn_kernel(
    const float* __restrict__ qkv, float* __restrict__ att) {
    int warp = (blockIdx.x * blockDim.x + threadIdx.x) >> 5;
    int lane = threadIdx.x & 31;
    int t = warp & (TT - 1);
    int h = (warp >> 11) & 3;
    int b = warp >> 13;

    const float* qp = qkv + (size_t)(b * TT + t) * (3 * DD) + h * HD;
    float q0 = qp[lane] * 0.125f;        // 1/sqrt(HD)=0.125 folded into q
    float q1 = qp[lane + 32] * 0.125f;

    const float* kvb = qkv + (size_t)b * TT * (3 * DD) + DD + h * HD;

    float m = -1e30f, lsum = 0.f, a0 = 0.f, a1 = 0.f;
    for (int s = 0; s <= t; s++) {
        const float* kp = kvb + (size_t)s * (3 * DD);
        float part = q0 * kp[lane] + q1 * kp[lane + 32];
        #pragma unroll
        for (int o = 16; o; o >>= 1) part += __shfl_xor_sync(0xffffffffu, part, o);
        float nm   = fmaxf(m, part);
        float corr = __expf(m - nm);
        float p    = __expf(part - nm);
        const float* vp = kp + DD;
        lsum = lsum * corr + p;
        a0 = a0 * corr + p * vp[lane];
        a1 = a1 * corr + p * vp[lane + 32];
        m = nm;
    }
    float inv = 1.f / lsum;
    float* op = att + (size_t)(b * TT + t) * DD + h * HD;
    op[lane]      = a0 * inv;
    op[lane + 32] = a1 * inv;
}

// ---------------------------------------------------------------------------
// q_scores[b,q,t] = dot(queries[q], xn[b,t]) / 16 — one block per (b,q)
// ---------------------------------------------------------------------------
__global__ __launch_bounds__(256) void qscore_kernel(
    const float* __restrict__ xn, const float* __restrict__ queries,
    float* __restrict__ qattn) {
    int b = blockIdx.x >> 7;
    int q = blockIdx.x & 127;
    int lane = threadIdx.x & 31, w = threadIdx.x >> 5;
    float qv[8];
    #pragma unroll
    for (int j = 0; j < 8; j++) qv[j] = queries[q * DD + lane + 32 * j];
    const float* xb = xn + (size_t)b * TT * DD;
    float* orow = qattn + (size_t)(b * QQ + q) * TT;
    for (int t = w; t < TT; t += 8) {
        const float* xr = xb + (size_t)t * DD;
        float part = 0.f;
        #pragma unroll
        for (int j = 0; j < 8; j++) part += qv[j] * xr[lane + 32 * j];
        #pragma unroll
        for (int o = 16; o; o >>= 1) part += __shfl_xor_sync(0xffffffffu, part, o);
        if (lane == 0) orow[t] = part * 0.0625f;
    }
}

// ---------------------------------------------------------------------------
// Softmax over last dim (2048), in place. One block per row.
// ---------------------------------------------------------------------------
__global__ __launch_bounds__(256) void softmax2048_kernel(float* __restrict__ p) {
    float* row = p + (size_t)blockIdx.x * TT;
    int tid = threadIdx.x;
    float v[8];
    float mx = -1e30f;
    #pragma unroll
    for (int j = 0; j < 8; j++) { v[j] = row[tid + 256 * j]; mx = fmaxf(mx, v[j]); }
    mx = blockReduceMax256(mx);
    float s = 0.f;
    #pragma unroll
    for (int j = 0; j < 8; j++) { v[j] = __expf(v[j] - mx); s += v[j]; }
    s = blockReduceSum256(s);
    float inv = 1.f / s;
    #pragma unroll
    for (int j = 0; j < 8; j++) row[tid + 256 * j] = v[j] * inv;
}

// ---------------------------------------------------------------------------
// selected[b,q,:] = q_attn[b,q,:] @ xn[b];  bits = sigmoid(selected@w + b)
// fused: one block per (b,q); thread d owns dim d.
// ---------------------------------------------------------------------------
__global__ __launch_bounds__(256) void selbits_kernel(
    const float* __restrict__ qattn, const float* __restrict__ xn,
    const float* __restrict__ outp_w, const float* __restrict__ outp_b,
    float* __restrict__ pairs) {
    int b = blockIdx.x >> 7;
    int q = blockIdx.x & 127;
    int d = threadIdx.x;
    const float* wrow = qattn + (size_t)(b * QQ + q) * TT;
    const float* xb = xn + (size_t)b * TT * DD + d;
    float acc = 0.f;
    for (int t = 0; t < TT; t += 4) {
        acc += wrow[t]     * xb[(size_t)t * DD];
        acc += wrow[t + 1] * xb[(size_t)(t + 1) * DD];
        acc += wrow[t + 2] * xb[(size_t)(t + 2) * DD];
        acc += wrow[t + 3] * xb[(size_t)(t + 3) * DD];
    }
    float s = blockReduceSum256(acc * outp_w[d]);
    if (d == 0)
        pairs[b * QQ + q] = 1.f / (1.f + __expf(-(s + outp_b[0])));
}

// ---------------------------------------------------------------------------
// 64-step recurrent MLP scan. One block per batch row, 64 threads.
// ---------------------------------------------------------------------------
__global__ __launch_bounds__(64) void scan_kernel(
    const float* __restrict__ pairs,
    const float* __restrict__ w1, const float* __restrict__ b1,
    const float* __restrict__ w2, const float* __restrict__ b2,
    const float* __restrict__ w3, const float* __restrict__ b3,
    float* __restrict__ sum_all) {
    int b = blockIdx.x;
    int j = threadIdx.x;
    __shared__ float h1[64], h2[64];
    __shared__ float carry;
    if (j == 0) carry = 0.f;

    float w1a = w1[j], w1b = w1[64 + j], w1c = w1[128 + j], bb1 = b1[j];
    float w2c[64];
    #pragma unroll
    for (int k = 0; k < 64; k++) w2c[k] = w2[k * 64 + j];
    float bb2 = b2[j];
    __syncthreads();

    for (int i = 0; i < 64; i++) {
        float z0 = pairs[b * QQ + i * 2];
        float z1 = pairs[b * QQ + i * 2 + 1];
        float z2 = carry;
        h1[j] = fmaxf(0.f, z0 * w1a + z1 * w1b + z2 * w1c + bb1);
        __syncthreads();
        float acc = bb2;
        #pragma unroll
        for (int k = 0; k < 64; k++) acc += h1[k] * w2c[k];
        h2[j] = fmaxf(0.f, acc);
        __syncthreads();
        if (j == 0) {
            float o0 = b3[0], o1 = b3[1];
            #pragma unroll
            for (int k = 0; k < 64; k++) {
                o0 += h2[k] * w3[k * 2];
                o1 += h2[k] * w3[k * 2 + 1];
            }
            o0 = 1.f / (1.f + __expf(-o0));
            o1 = 1.f / (1.f + __expf(-o1));
            sum_all[b * 65 + i] = o0;
            carry = o1;
        }
        __syncthreads();
    }
    if (j == 0) sum_all[b * 65 + 64] = carry;
}

// ---------------------------------------------------------------------------
// Launch
// ---------------------------------------------------------------------------
extern "C" void kernel_launch(void* const* d_in, const int* in_sizes, int n_in,
                              void* d_out, int out_size) {
    const int*   tokens   = (const int*)  d_in[0];
    const float* embed    = (const float*)d_in[1];
    const float* ln1_w    = (const float*)d_in[2];
    const float* ln1_b    = (const float*)d_in[3];
    const float* qkv_w    = (const float*)d_in[4];
    const float* qkv_b    = (const float*)d_in[5];
    const float* proj_w   = (const float*)d_in[6];
    const float* proj_b   = (const float*)d_in[7];
    const float* ln2_w    = (const float*)d_in[8];
    const float* ln2_b    = (const float*)d_in[9];
    const float* ffn1_w   = (const float*)d_in[10];
    const float* ffn1_b   = (const float*)d_in[11];
    const float* ffn2_w   = (const float*)d_in[12];
    const float* ffn2_b   = (const float*)d_in[13];
    const float* lnf_w    = (const float*)d_in[14];
    const float* lnf_b    = (const float*)d_in[15];
    const float* queries  = (const float*)d_in[16];
    const float* outp_w   = (const float*)d_in[17];
    const float* outp_b   = (const float*)d_in[18];
    const float* mlp_w1   = (const float*)d_in[19];
    const float* mlp_b1   = (const float*)d_in[20];
    const float* mlp_w2   = (const float*)d_in[21];
    const float* mlp_b2   = (const float*)d_in[22];
    const float* mlp_w3   = (const float*)d_in[23];
    const float* mlp_b3   = (const float*)d_in[24];

    float* out     = (float*)d_out;
    float* sum_all = out;                  // (B,65)   = 260
    float* pairs   = out + 260;            // (B,64,2) = 512
    float* qattn   = out + 772;            // (B,128,2048)

    float *px, *pxn, *pqkv, *patt, *ph;
    cudaGetSymbolAddress((void**)&px,   g_x);
    cudaGetSymbolAddress((void**)&pxn,  g_xn);
    cudaGetSymbolAddress((void**)&pqkv, g_qkv);
    cudaGetSymbolAddress((void**)&patt, g_att);
    cudaGetSymbolAddress((void**)&ph,   g_h);

    const int ROWS = BB * TT;  // 8192

    embed_kernel<<<ROWS, 256>>>(tokens, embed, px);

    for (int l = 0; l < LL; l++) {
        ln_kernel<<<ROWS, 256>>>(px, ln1_w + l * DD, ln1_b + l * DD, pxn);
        gemm_kernel<0><<<dim3(12, ROWS / 64), 256>>>(
            pxn, qkv_w + (size_t)l * DD * 3 * DD, qkv_b + l * 3 * DD, pqkv,
            ROWS, 3 * DD, DD);
        rope_kernel<<<ROWS, 256>>>(pqkv);
        attn_kernel<<<(BB * HH * TT) / 4, 128>>>(pqkv, patt);
        gemm_kernel<2><<<dim3(4, ROWS / 64), 256>>>(
            patt, proj_w + (size_t)l * DD * DD, proj_b + l * DD, px,
            ROWS, DD, DD);
        ln_kernel<<<ROWS, 256>>>(px, ln2_w + l * DD, ln2_b + l * DD, pxn);
        gemm_kernel<1><<<dim3(16, ROWS / 64), 256>>>(
            pxn, ffn1_w + (size_t)l * DD * 4 * DD, ffn1_b + l * 4 * DD, ph,
            ROWS, 4 * DD, DD);
        gemm_kernel<2><<<dim3(4, ROWS / 64), 256>>>(
            ph, ffn2_w + (size_t)l * 4 * DD * DD, ffn2_b + l * DD, px,
            ROWS, DD, 4 * DD);
    }

    ln_kernel<<<ROWS, 256>>>(px, lnf_w, lnf_b, pxn);
    qscore_kernel<<<BB * QQ, 256>>>(pxn, queries, qattn);
    softmax2048_kernel<<<BB * QQ, 256>>>(qattn);
    selbits_kernel<<<BB * QQ, 256>>>(qattn, pxn, outp_w, outp_b, pairs);
    scan_kernel<<<BB, 64>>>(pairs, mlp_w1, mlp_b1, mlp_w2, mlp_b2,
                            mlp_w3, mlp_b3, sum_all);
}

// round 3
// speedup vs baseline: 2.0321x; 2.0321x over previous
#include <cuda_runtime.h>
#include <cuda_bf16.h>
#include <math.h>

// ---------------------------------------------------------------------------
// Model dims (compile-time)
// ---------------------------------------------------------------------------
#define BB 4
#define TT 2048
#define DD 256
#define HH 4
#define HD 64
#define LL 2
#define QQ 128          // MAX_BITS*2 out queries

// ---------------------------------------------------------------------------
// Scratch (device globals; no runtime allocation allowed)
// ---------------------------------------------------------------------------
__device__ float g_x  [BB*TT*DD];        // residual stream
__device__ float g_xn [BB*TT*DD];        // layernormed activations
__device__ float g_qkv[BB*TT*3*DD];      // qkv projections
__device__ float g_att[BB*TT*DD];        // attention output (b,t,h,hd)
__device__ float g_h  [BB*TT*4*DD];      // ffn hidden

// ---------------------------------------------------------------------------
// Reductions
// ---------------------------------------------------------------------------
__device__ __forceinline__ float blockReduceSum256(float v) {
    __shared__ float sh[8];
    int lane = threadIdx.x & 31, wid = threadIdx.x >> 5;
    #pragma unroll
    for (int o = 16; o; o >>= 1) v += __shfl_xor_sync(0xffffffffu, v, o);
    if (lane == 0) sh[wid] = v;
    __syncthreads();
    if (wid == 0) {
        float r = (lane < 8) ? sh[lane] : 0.f;
        #pragma unroll
        for (int o = 4; o; o >>= 1) r += __shfl_xor_sync(0xffffffffu, r, o);
        if (lane == 0) sh[0] = r;
    }
    __syncthreads();
    float r = sh[0];
    __syncthreads();
    return r;
}

__device__ __forceinline__ float blockReduceMax256(float v) {
    __shared__ float sh[8];
    int lane = threadIdx.x & 31, wid = threadIdx.x >> 5;
    #pragma unroll
    for (int o = 16; o; o >>= 1) v = fmaxf(v, __shfl_xor_sync(0xffffffffu, v, o));
    if (lane == 0) sh[wid] = v;
    __syncthreads();
    if (wid == 0) {
        float r = (lane < 8) ? sh[lane] : -1e30f;
        #pragma unroll
        for (int o = 4; o; o >>= 1) r = fmaxf(r, __shfl_xor_sync(0xffffffffu, r, o));
        if (lane == 0) sh[0] = r;
    }
    __syncthreads();
    float r = sh[0];
    __syncthreads();
    return r;
}

// ---------------------------------------------------------------------------
// Embedding lookup
// ---------------------------------------------------------------------------
__global__ void embed_kernel(const int* __restrict__ tokens,
                             const float* __restrict__ embed,
                             float* __restrict__ x) {
    int row = blockIdx.x;
    int d   = threadIdx.x;
    int tok = tokens[row];
    x[(size_t)row * DD + d] = embed[(size_t)tok * DD + d];
}

// ---------------------------------------------------------------------------
// LayerNorm over D=256, one block per row
// ---------------------------------------------------------------------------
__global__ void ln_kernel(const float* __restrict__ x,
                          const float* __restrict__ w,
                          const float* __restrict__ b,
                          float* __restrict__ y) {
    int row = blockIdx.x;
    int d   = threadIdx.x;
    float v  = x[(size_t)row * DD + d];
    float mu = blockReduceSum256(v) * (1.f / DD);
    float dv = v - mu;
    float var = blockReduceSum256(dv * dv) * (1.f / DD);
    float r = rsqrtf(var + 1e-5f);
    y[(size_t)row * DD + d] = dv * r * w[d] + b[d];
}

// ---------------------------------------------------------------------------
// GEMM: C[M,N] = A[M,K] @ B[K,N] + bias
//   EPI 0: bias;  EPI 1: bias+gelu;  EPI 2: bias+residual accumulate
// 64x64 block tile, K-tile 16, 256 threads, 4x4 per thread.
// ---------------------------------------------------------------------------
template <int EPI>
__global__ __launch_bounds__(256) void gemm_kernel(
    const float* __restrict__ A, const float* __restrict__ B,
    const float* __restrict__ bias, float* __restrict__ C,
    int M, int N, int K) {
    __shared__ float As[16][64];
    __shared__ float Bs[16][64];
    int tid = threadIdx.x;
    int bm = blockIdx.y * 64, bn = blockIdx.x * 64;

    int arow = tid >> 2, acol = (tid & 3) * 4;
    int brow = tid >> 4, bcol = (tid & 15) * 4;
    int ty = tid >> 4, tx = tid & 15;

    float acc[4][4] = {};

    for (int k0 = 0; k0 < K; k0 += 16) {
        float4 av = *(const float4*)(A + (size_t)(bm + arow) * K + k0 + acol);
        As[acol + 0][arow] = av.x;
        As[acol + 1][arow] = av.y;
        As[acol + 2][arow] = av.z;
        As[acol + 3][arow] = av.w;
        *(float4*)&Bs[brow][bcol] =
            *(const float4*)(B + (size_t)(k0 + brow) * N + bn + bcol);
        __syncthreads();
        #pragma unroll
        for (int kk = 0; kk < 16; kk++) {
            float4 a = *(const float4*)&As[kk][ty * 4];
            float4 bq = *(const float4*)&Bs[kk][tx * 4];
            float ar[4] = {a.x, a.y, a.z, a.w};
            float br[4] = {bq.x, bq.y, bq.z, bq.w};
            #pragma unroll
            for (int i = 0; i < 4; i++)
                #pragma unroll
                for (int j = 0; j < 4; j++)
                    acc[i][j] += ar[i] * br[j];
        }
        __syncthreads();
    }

    #pragma unroll
    for (int i = 0; i < 4; i++) {
        int r = bm + ty * 4 + i;
        #pragma unroll
        for (int j = 0; j < 4; j++) {
            int c = bn + tx * 4 + j;
            float v = acc[i][j] + bias[c];
            if (EPI == 1) v = 0.5f * v * (1.f + erff(v * 0.70710678118654752f));
            if (EPI == 2) v += C[(size_t)r * N + c];
            C[(size_t)r * N + c] = v;
        }
    }
}

// ---------------------------------------------------------------------------
// RoPE applied in-place to q and k parts of g_qkv.
// ---------------------------------------------------------------------------
__global__ void rope_kernel(float* __restrict__ qkv) {
    int idx  = blockIdx.x * blockDim.x + threadIdx.x;
    int d    = idx & 31;
    int h    = (idx >> 5) & 3;
    int part = (idx >> 7) & 1;
    int row  = idx >> 8;           // b*T + t
    int t    = row & (TT - 1);
    float inv = powf(10000.f, -(float)d * (1.f / 32.f));
    float ang = (float)t * inv;
    float s, c;
    sincosf(ang, &s, &c);
    float* p = qkv + (size_t)row * (3 * DD) + part * DD + h * HD;
    float x0 = p[d], x1 = p[d + 32];
    p[d]      = x0 * c - x1 * s;
    p[d + 32] = x1 * c + x0 * s;
}

// ---------------------------------------------------------------------------
// Tiled flash attention. One block per (b, h, 64-query tile).
// 256 threads as 16x16; each thread owns a 4x4 fragment.
// smem (dynamic, 66560B): Qs[64][64] K-major, Ks[64][64] K-major,
//                         Vs[64][64] natural, Ps[64][68] (s-major, padded)
// ---------------------------------------------------------------------------
#define PS_STRIDE 68
#define FATTN_SMEM ((64*64*3 + 64*PS_STRIDE) * 4)

__global__ __launch_bounds__(256) void fattn_kernel(
    const float* __restrict__ qkv, float* __restrict__ att) {
    extern __shared__ float sm[];
    float* Qs = sm;                 // [k][i], stride 64
    float* Ks = sm + 4096;          // [k][j], stride 64
    float* Vs = sm + 8192;          // [s][d], stride 64
    float* Ps = sm + 12288;         // [s][i], stride 68

    int qt = blockIdx.x;            // 0..31
    int h  = blockIdx.y;
    int b  = blockIdx.z;
    int tid = threadIdx.x;
    int tx = tid & 15, ty = tid >> 4;

    // loader indices: each thread covers row lr, 16 consecutive floats
    int lr = tid >> 2;              // 0..63
    int lc = (tid & 3) * 16;        // 0,16,32,48

    const float* base = qkv + (size_t)b * TT * (3 * DD);

    // ---- load Q tile transposed (scaled by 1/sqrt(HD)=0.125) ----
    {
        const float* qrow = base + (size_t)(qt * 64 + lr) * (3 * DD) + h * HD + lc;
        #pragma unroll
        for (int m = 0; m < 4; m++) {
            float4 v = *(const float4*)(qrow + m * 4);
            int c = lc + m * 4;
            Qs[(c + 0) * 64 + lr] = v.x * 0.125f;
            Qs[(c + 1) * 64 + lr] = v.y * 0.125f;
            Qs[(c + 2) * 64 + lr] = v.z * 0.125f;
            Qs[(c + 3) * 64 + lr] = v.w * 0.125f;
        }
    }

    float m_i[4], l_i[4], acc[4][4];
    #pragma unroll
    for (int i = 0; i < 4; i++) {
        m_i[i] = -1e30f; l_i[i] = 0.f;
        #pragma unroll
        for (int j = 0; j < 4; j++) acc[i][j] = 0.f;
    }

    for (int kt = 0; kt <= qt; kt++) {
        __syncthreads();   // previous PV done reading Ks/Vs/Ps
        // ---- load K tile transposed + V tile ----
        {
            const float* krow = base + (size_t)(kt * 64 + lr) * (3 * DD) + DD + h * HD + lc;
            #pragma unroll
            for (int m = 0; m < 4; m++) {
                float4 v = *(const float4*)(krow + m * 4);
                int c = lc + m * 4;
                Ks[(c + 0) * 64 + lr] = v.x;
                Ks[(c + 1) * 64 + lr] = v.y;
                Ks[(c + 2) * 64 + lr] = v.z;
                Ks[(c + 3) * 64 + lr] = v.w;
            }
            const float* vrow = base + (size_t)(kt * 64 + lr) * (3 * DD) + 2 * DD + h * HD + lc;
            #pragma unroll
            for (int m = 0; m < 4; m++) {
                *(float4*)&Vs[lr * 64 + lc + m * 4] = *(const float4*)(vrow + m * 4);
            }
        }
        __syncthreads();

        // ---- S = Q K^T (64x64x64) ----
        float s[4][4] = {};
        #pragma unroll 4
        for (int k = 0; k < 64; k++) {
            float4 qa = *(const float4*)&Qs[k * 64 + ty * 4];
            float4 kb = *(const float4*)&Ks[k * 64 + tx * 4];
            float ar[4] = {qa.x, qa.y, qa.z, qa.w};
            float br[4] = {kb.x, kb.y, kb.z, kb.w};
            #pragma unroll
            for (int i = 0; i < 4; i++)
                #pragma unroll
                for (int j = 0; j < 4; j++)
                    s[i][j] += ar[i] * br[j];
        }

        // causal mask on diagonal tile
        if (kt == qt) {
            #pragma unroll
            for (int i = 0; i < 4; i++)
                #pragma unroll
                for (int j = 0; j < 4; j++)
                    if (tx * 4 + j > ty * 4 + i) s[i][j] = -1e30f;
        }

        // ---- online softmax update (per row, reduced over the 16 tx lanes) ----
        #pragma unroll
        for (int i = 0; i < 4; i++) {
            float rm = fmaxf(fmaxf(s[i][0], s[i][1]), fmaxf(s[i][2], s[i][3]));
            #pragma unroll
            for (int o = 8; o; o >>= 1) rm = fmaxf(rm, __shfl_xor_sync(0xffffffffu, rm, o));
            float nm = fmaxf(m_i[i], rm);
            float corr = __expf(m_i[i] - nm);
            m_i[i] = nm;
            float rs = 0.f;
            #pragma unroll
            for (int j = 0; j < 4; j++) {
                float p = __expf(s[i][j] - nm);
                Ps[(tx * 4 + j) * PS_STRIDE + ty * 4 + i] = p;
                rs += p;
            }
            #pragma unroll
            for (int o = 8; o; o >>= 1) rs += __shfl_xor_sync(0xffffffffu, rs, o);
            l_i[i] = l_i[i] * corr + rs;
            #pragma unroll
            for (int j = 0; j < 4; j++) acc[i][j] *= corr;
        }
        __syncthreads();

        // ---- O += P V (64x64x64) ----
        #pragma unroll 4
        for (int ss = 0; ss < 64; ss++) {
            float4 pa = *(const float4*)&Ps[ss * PS_STRIDE + ty * 4];
            float4 vb = *(const float4*)&Vs[ss * 64 + tx * 4];
            float pr[4] = {pa.x, pa.y, pa.z, pa.w};
            float vr[4] = {vb.x, vb.y, vb.z, vb.w};
            #pragma unroll
            for (int i = 0; i < 4; i++)
                #pragma unroll
                for (int j = 0; j < 4; j++)
                    acc[i][j] += pr[i] * vr[j];
        }
    }

    // ---- epilogue ----
    #pragma unroll
    for (int i = 0; i < 4; i++) {
        float inv = 1.f / l_i[i];
        int t = qt * 64 + ty * 4 + i;
        float4 o;
        o.x = acc[i][0] * inv; o.y = acc[i][1] * inv;
        o.z = acc[i][2] * inv; o.w = acc[i][3] * inv;
        *(float4*)(att + (size_t)(b * TT + t) * DD + h * HD + tx * 4) = o;
    }
}

// ---------------------------------------------------------------------------
// q_scores[b,q,t] = dot(queries[q], xn[b,t]) / 16
// ---------------------------------------------------------------------------
__global__ __launch_bounds__(256) void qscore_kernel(
    const float* __restrict__ xn, const float* __restrict__ queries,
    float* __restrict__ qattn) {
    int b = blockIdx.x >> 7;
    int q = blockIdx.x & 127;
    int lane = threadIdx.x & 31, w = threadIdx.x >> 5;
    float qv[8];
    #pragma unroll
    for (int j = 0; j < 8; j++) qv[j] = queries[q * DD + lane + 32 * j];
    const float* xb = xn + (size_t)b * TT * DD;
    float* orow = qattn + (size_t)(b * QQ + q) * TT;
    for (int t = w; t < TT; t += 8) {
        const float* xr = xb + (size_t)t * DD;
        float part = 0.f;
        #pragma unroll
        for (int j = 0; j < 8; j++) part += qv[j] * xr[lane + 32 * j];
        #pragma unroll
        for (int o = 16; o; o >>= 1) part += __shfl_xor_sync(0xffffffffu, part, o);
        if (lane == 0) orow[t] = part * 0.0625f;
    }
}

// ---------------------------------------------------------------------------
// Softmax over last dim (2048), in place. One block per row.
// ---------------------------------------------------------------------------
__global__ __launch_bounds__(256) void softmax2048_kernel(float* __restrict__ p) {
    float* row = p + (size_t)blockIdx.x * TT;
    int tid = threadIdx.x;
    float v[8];
    float mx = -1e30f;
    #pragma unroll
    for (int j = 0; j < 8; j++) { v[j] = row[tid + 256 * j]; mx = fmaxf(mx, v[j]); }
    mx = blockReduceMax256(mx);
    float s = 0.f;
    #pragma unroll
    for (int j = 0; j < 8; j++) { v[j] = __expf(v[j] - mx); s += v[j]; }
    s = blockReduceSum256(s);
    float inv = 1.f / s;
    #pragma unroll
    for (int j = 0; j < 8; j++) row[tid + 256 * j] = v[j] * inv;
}

// ---------------------------------------------------------------------------
// selected[b,q,:] = q_attn[b,q,:] @ xn[b];  bits = sigmoid(selected@w + b)
// ---------------------------------------------------------------------------
__global__ __launch_bounds__(256) void selbits_kernel(
    const float* __restrict__ qattn, const float* __restrict__ xn,
    const float* __restrict__ outp_w, const float* __restrict__ outp_b,
    float* __restrict__ pairs) {
    int b = blockIdx.x >> 7;
    int q = blockIdx.x & 127;
    int d = threadIdx.x;
    const float* wrow = qattn + (size_t)(b * QQ + q) * TT;
    const float* xb = xn + (size_t)b * TT * DD + d;
    float acc = 0.f;
    for (int t = 0; t < TT; t += 4) {
        acc += wrow[t]     * xb[(size_t)t * DD];
        acc += wrow[t + 1] * xb[(size_t)(t + 1) * DD];
        acc += wrow[t + 2] * xb[(size_t)(t + 2) * DD];
        acc += wrow[t + 3] * xb[(size_t)(t + 3) * DD];
    }
    float s = blockReduceSum256(acc * outp_w[d]);
    if (d == 0)
        pairs[b * QQ + q] = 1.f / (1.f + __expf(-(s + outp_b[0])));
}

// ---------------------------------------------------------------------------
// 64-step recurrent MLP scan. One block per batch row, 64 threads.
// ---------------------------------------------------------------------------
__global__ __launch_bounds__(64) void scan_kernel(
    const float* __restrict__ pairs,
    const float* __restrict__ w1, const float* __restrict__ b1,
    const float* __restrict__ w2, const float* __restrict__ b2,
    const float* __restrict__ w3, const float* __restrict__ b3,
    float* __restrict__ sum_all) {
    int b = blockIdx.x;
    int j = threadIdx.x;
    __shared__ float h1[64], h2[64];
    __shared__ float carry;
    if (j == 0) carry = 0.f;

    float w1a = w1[j], w1b = w1[64 + j], w1c = w1[128 + j], bb1 = b1[j];
    float w2c[64];
    #pragma unroll
    for (int k = 0; k < 64; k++) w2c[k] = w2[k * 64 + j];
    float bb2 = b2[j];
    __syncthreads();

    for (int i = 0; i < 64; i++) {
        float z0 = pairs[b * QQ + i * 2];
        float z1 = pairs[b * QQ + i * 2 + 1];
        float z2 = carry;
        h1[j] = fmaxf(0.f, z0 * w1a + z1 * w1b + z2 * w1c + bb1);
        __syncthreads();
        float acc = bb2;
        #pragma unroll
        for (int k = 0; k < 64; k++) acc += h1[k] * w2c[k];
        h2[j] = fmaxf(0.f, acc);
        __syncthreads();
        if (j == 0) {
            float o0 = b3[0], o1 = b3[1];
            #pragma unroll
            for (int k = 0; k < 64; k++) {
                o0 += h2[k] * w3[k * 2];
                o1 += h2[k] * w3[k * 2 + 1];
            }
            o0 = 1.f / (1.f + __expf(-o0));
            o1 = 1.f / (1.f + __expf(-o1));
            sum_all[b * 65 + i] = o0;
            carry = o1;
        }
        __syncthreads();
    }
    if (j == 0) sum_all[b * 65 + 64] = carry;
}

// ---------------------------------------------------------------------------
// Launch
// ---------------------------------------------------------------------------
extern "C" void kernel_launch(void* const* d_in, const int* in_sizes, int n_in,
                              void* d_out, int out_size) {
    const int*   tokens   = (const int*)  d_in[0];
    const float* embed    = (const float*)d_in[1];
    const float* ln1_w    = (const float*)d_in[2];
    const float* ln1_b    = (const float*)d_in[3];
    const float* qkv_w    = (const float*)d_in[4];
    const float* qkv_b    = (const float*)d_in[5];
    const float* proj_w   = (const float*)d_in[6];
    const float* proj_b   = (const float*)d_in[7];
    const float* ln2_w    = (const float*)d_in[8];
    const float* ln2_b    = (const float*)d_in[9];
    const float* ffn1_w   = (const float*)d_in[10];
    const float* ffn1_b   = (const float*)d_in[11];
    const float* ffn2_w   = (const float*)d_in[12];
    const float* ffn2_b   = (const float*)d_in[13];
    const float* lnf_w    = (const float*)d_in[14];
    const float* lnf_b    = (const float*)d_in[15];
    const float* queries  = (const float*)d_in[16];
    const float* outp_w   = (const float*)d_in[17];
    const float* outp_b   = (const float*)d_in[18];
    const float* mlp_w1   = (const float*)d_in[19];
    const float* mlp_b1   = (const float*)d_in[20];
    const float* mlp_w2   = (const float*)d_in[21];
    const float* mlp_b2   = (const float*)d_in[22];
    const float* mlp_w3   = (const float*)d_in[23];
    const float* mlp_b3   = (const float*)d_in[24];

    float* out     = (float*)d_out;
    float* sum_all = out;                  // (B,65)   = 260
    float* pairs   = out + 260;            // (B,64,2) = 512
    float* qattn   = out + 772;            // (B,128,2048)

    float *px, *pxn, *pqkv, *patt, *ph;
    cudaGetSymbolAddress((void**)&px,   g_x);
    cudaGetSymbolAddress((void**)&pxn,  g_xn);
    cudaGetSymbolAddress((void**)&pqkv, g_qkv);
    cudaGetSymbolAddress((void**)&patt, g_att);
    cudaGetSymbolAddress((void**)&ph,   g_h);

    cudaFuncSetAttribute(fattn_kernel,
                         cudaFuncAttributeMaxDynamicSharedMemorySize, FATTN_SMEM);

    const int ROWS = BB * TT;  // 8192

    embed_kernel<<<ROWS, 256>>>(tokens, embed, px);

    for (int l = 0; l < LL; l++) {
        ln_kernel<<<ROWS, 256>>>(px, ln1_w + l * DD, ln1_b + l * DD, pxn);
        gemm_kernel<0><<<dim3(12, ROWS / 64), 256>>>(
            pxn, qkv_w + (size_t)l * DD * 3 * DD, qkv_b + l * 3 * DD, pqkv,
            ROWS, 3 * DD, DD);
        rope_kernel<<<ROWS, 256>>>(pqkv);
        fattn_kernel<<<dim3(TT / 64, HH, BB), 256, FATTN_SMEM>>>(pqkv, patt);
        gemm_kernel<2><<<dim3(4, ROWS / 64), 256>>>(
            patt, proj_w + (size_t)l * DD * DD, proj_b + l * DD, px,
            ROWS, DD, DD);
        ln_kernel<<<ROWS, 256>>>(px, ln2_w + l * DD, ln2_b + l * DD, pxn);
        gemm_kernel<1><<<dim3(16, ROWS / 64), 256>>>(
            pxn, ffn1_w + (size_t)l * DD * 4 * DD, ffn1_b + l * 4 * DD, ph,
            ROWS, 4 * DD, DD);
        gemm_kernel<2><<<dim3(4, ROWS / 64), 256>>>(
            ph, ffn2_w + (size_t)l * 4 * DD * DD, ffn2_b + l * DD, px,
            ROWS, DD, 4 * DD);
    }

    ln_kernel<<<ROWS, 256>>>(px, lnf_w, lnf_b, pxn);
    qscore_kernel<<<BB * QQ, 256>>>(pxn, queries, qattn);
    softmax2048_kernel<<<BB * QQ, 256>>>(qattn);
    selbits_kernel<<<BB * QQ, 256>>>(qattn, pxn, outp_w, outp_b, pairs);
    scan_kernel<<<BB, 64>>>(pairs, mlp_w1, mlp_b1, mlp_w2, mlp_b2,
                            mlp_w3, mlp_b3, sum_all);
}

// round 4
// speedup vs baseline: 2.3080x; 1.1357x over previous
#include <cuda_runtime.h>
#include <cuda_bf16.h>
#include <math.h>

// ---------------------------------------------------------------------------
// Model dims (compile-time)
// ---------------------------------------------------------------------------
#define BB 4
#define TT 2048
#define DD 256
#define HH 4
#define HD 64
#define LL 2
#define QQ 128          // MAX_BITS*2 out queries

// ---------------------------------------------------------------------------
// Scratch (device globals; no runtime allocation allowed)
// ---------------------------------------------------------------------------
__device__ float g_x  [BB*TT*DD];        // residual stream
__device__ float g_xn [BB*TT*DD];        // layernormed activations
__device__ float g_qkv[BB*TT*3*DD];      // qkv projections
__device__ float g_att[BB*TT*DD];        // attention output (b,t,h,hd)
__device__ float g_h  [BB*TT*4*DD];      // ffn hidden

// ---------------------------------------------------------------------------
// Reductions
// ---------------------------------------------------------------------------
__device__ __forceinline__ float blockReduceSum256(float v) {
    __shared__ float sh[8];
    int lane = threadIdx.x & 31, wid = threadIdx.x >> 5;
    #pragma unroll
    for (int o = 16; o; o >>= 1) v += __shfl_xor_sync(0xffffffffu, v, o);
    if (lane == 0) sh[wid] = v;
    __syncthreads();
    if (wid == 0) {
        float r = (lane < 8) ? sh[lane] : 0.f;
        #pragma unroll
        for (int o = 4; o; o >>= 1) r += __shfl_xor_sync(0xffffffffu, r, o);
        if (lane == 0) sh[0] = r;
    }
    __syncthreads();
    float r = sh[0];
    __syncthreads();
    return r;
}

__device__ __forceinline__ float blockReduceMax256(float v) {
    __shared__ float sh[8];
    int lane = threadIdx.x & 31, wid = threadIdx.x >> 5;
    #pragma unroll
    for (int o = 16; o; o >>= 1) v = fmaxf(v, __shfl_xor_sync(0xffffffffu, v, o));
    if (lane == 0) sh[wid] = v;
    __syncthreads();
    if (wid == 0) {
        float r = (lane < 8) ? sh[lane] : -1e30f;
        #pragma unroll
        for (int o = 4; o; o >>= 1) r = fmaxf(r, __shfl_xor_sync(0xffffffffu, r, o));
        if (lane == 0) sh[0] = r;
    }
    __syncthreads();
    float r = sh[0];
    __syncthreads();
    return r;
}

// ---------------------------------------------------------------------------
// Embedding lookup
// ---------------------------------------------------------------------------
__global__ void embed_kernel(const int* __restrict__ tokens,
                             const float* __restrict__ embed,
                             float* __restrict__ x) {
    int row = blockIdx.x;
    int d   = threadIdx.x;
    int tok = tokens[row];
    x[(size_t)row * DD + d] = embed[(size_t)tok * DD + d];
}

// ---------------------------------------------------------------------------
// LayerNorm over D=256, one block per row
// ---------------------------------------------------------------------------
__global__ void ln_kernel(const float* __restrict__ x,
                          const float* __restrict__ w,
                          const float* __restrict__ b,
                          float* __restrict__ y) {
    int row = blockIdx.x;
    int d   = threadIdx.x;
    float v  = x[(size_t)row * DD + d];
    float mu = blockReduceSum256(v) * (1.f / DD);
    float dv = v - mu;
    float var = blockReduceSum256(dv * dv) * (1.f / DD);
    float r = rsqrtf(var + 1e-5f);
    y[(size_t)row * DD + d] = dv * r * w[d] + b[d];
}

// ---------------------------------------------------------------------------
// GEMM: C[M,N] = A[M,K] @ B[K,N] + bias
//   EPI 0: bias;  EPI 1: bias+gelu;  EPI 2: bias+residual accumulate
// Block tile 128 x TN (TN in {64,128}), K-tile 8, 256 threads.
// Per thread 8xNJ (NJ = TN/16). Register-prefetch double buffering.
// ---------------------------------------------------------------------------
template <int TN, int EPI>
__global__ __launch_bounds__(256) void gemm128_kernel(
    const float* __restrict__ A, const float* __restrict__ B,
    const float* __restrict__ bias, float* __restrict__ C,
    int M, int N, int K) {
    constexpr int NJ = TN / 16;
    __shared__ float As[2][8][128];
    __shared__ float Bs[2][8][TN];
    const int tid = threadIdx.x;
    const int bm = blockIdx.y * 128, bn = blockIdx.x * TN;
    const int tx = tid & 15, ty = tid >> 4;

    const int ar = tid >> 1, ac = (tid & 1) * 4;
    int br, bc; bool bact;
    if (TN == 128) { br = tid >> 5; bc = (tid & 31) * 4; bact = true; }
    else           { br = tid >> 4; bc = (tid & 15) * 4; bact = (tid < 128); }

    const int NT = K >> 3;
    float acc[8][NJ];
    #pragma unroll
    for (int i = 0; i < 8; i++)
        #pragma unroll
        for (int j = 0; j < NJ; j++) acc[i][j] = 0.f;

    {   // stage 0
        float4 av = *(const float4*)(A + (size_t)(bm + ar) * K + ac);
        As[0][ac + 0][ar] = av.x; As[0][ac + 1][ar] = av.y;
        As[0][ac + 2][ar] = av.z; As[0][ac + 3][ar] = av.w;
        if (bact)
            *(float4*)&Bs[0][br][bc] =
                *(const float4*)(B + (size_t)br * N + bn + bc);
    }
    __syncthreads();

    for (int kt = 0; kt < NT; kt++) {
        int cur = kt & 1;
        float4 av, bv;
        if (kt + 1 < NT) {
            av = *(const float4*)(A + (size_t)(bm + ar) * K + (kt + 1) * 8 + ac);
            if (bact)
                bv = *(const float4*)(B + (size_t)((kt + 1) * 8 + br) * N + bn + bc);
        }
        #pragma unroll
        for (int kk = 0; kk < 8; kk++) {
            float a0[8], b0[NJ];
            *(float4*)&a0[0] = *(const float4*)&As[cur][kk][ty * 4];
            *(float4*)&a0[4] = *(const float4*)&As[cur][kk][64 + ty * 4];
            *(float4*)&b0[0] = *(const float4*)&Bs[cur][kk][tx * 4];
            if (TN == 128)
                *(float4*)&b0[4] = *(const float4*)&Bs[cur][kk][64 + tx * 4];
            #pragma unroll
            for (int i = 0; i < 8; i++)
                #pragma unroll
                for (int j = 0; j < NJ; j++)
                    acc[i][j] += a0[i] * b0[j];
        }
        if (kt + 1 < NT) {
            int nxt = cur ^ 1;
            As[nxt][ac + 0][ar] = av.x; As[nxt][ac + 1][ar] = av.y;
            As[nxt][ac + 2][ar] = av.z; As[nxt][ac + 3][ar] = av.w;
            if (bact) *(float4*)&Bs[nxt][br][bc] = bv;
            __syncthreads();
        }
    }

    #pragma unroll
    for (int i = 0; i < 8; i++) {
        int r = bm + ((i < 4) ? ty * 4 + i : 64 + ty * 4 + (i - 4));
        #pragma unroll
        for (int jq = 0; jq < NJ / 4; jq++) {
            int cbase = bn + ((jq == 0) ? tx * 4 : 64 + tx * 4);
            float vv[4];
            #pragma unroll
            for (int j = 0; j < 4; j++) {
                float v = acc[i][jq * 4 + j] + bias[cbase + j];
                if (EPI == 1) v = 0.5f * v * (1.f + erff(v * 0.70710678118654752f));
                if (EPI == 2) v += C[(size_t)r * N + cbase + j];
                vv[j] = v;
            }
            float4 o; o.x = vv[0]; o.y = vv[1]; o.z = vv[2]; o.w = vv[3];
            *(float4*)(C + (size_t)r * N + cbase) = o;
        }
    }
}

// ---------------------------------------------------------------------------
// RoPE applied in-place to q and k parts of g_qkv.
// ---------------------------------------------------------------------------
__global__ void rope_kernel(float* __restrict__ qkv) {
    int idx  = blockIdx.x * blockDim.x + threadIdx.x;
    int d    = idx & 31;
    int h    = (idx >> 5) & 3;
    int part = (idx >> 7) & 1;
    int row  = idx >> 8;           // b*T + t
    int t    = row & (TT - 1);
    float inv = powf(10000.f, -(float)d * (1.f / 32.f));
    float ang = (float)t * inv;
    float s, c;
    sincosf(ang, &s, &c);
    float* p = qkv + (size_t)row * (3 * DD) + part * DD + h * HD;
    float x0 = p[d], x1 = p[d + 32];
    p[d]      = x0 * c - x1 * s;
    p[d + 32] = x1 * c + x0 * s;
}

// ---------------------------------------------------------------------------
// Tiled flash attention. One block per (b, h, 64-query tile).
// ---------------------------------------------------------------------------
#define PS_STRIDE 68
#define FATTN_SMEM ((64*64*3 + 64*PS_STRIDE) * 4)

__global__ __launch_bounds__(256) void fattn_kernel(
    const float* __restrict__ qkv, float* __restrict__ att) {
    extern __shared__ float sm[];
    float* Qs = sm;                 // [k][i], stride 64
    float* Ks = sm + 4096;          // [k][j], stride 64
    float* Vs = sm + 8192;          // [s][d], stride 64
    float* Ps = sm + 12288;         // [s][i], stride 68

    int qt = blockIdx.x;
    int h  = blockIdx.y;
    int b  = blockIdx.z;
    int tid = threadIdx.x;
    int tx = tid & 15, ty = tid >> 4;

    int lr = tid >> 2;
    int lc = (tid & 3) * 16;

    const float* base = qkv + (size_t)b * TT * (3 * DD);

    {
        const float* qrow = base + (size_t)(qt * 64 + lr) * (3 * DD) + h * HD + lc;
        #pragma unroll
        for (int m = 0; m < 4; m++) {
            float4 v = *(const float4*)(qrow + m * 4);
            int c = lc + m * 4;
            Qs[(c + 0) * 64 + lr] = v.x * 0.125f;
            Qs[(c + 1) * 64 + lr] = v.y * 0.125f;
            Qs[(c + 2) * 64 + lr] = v.z * 0.125f;
            Qs[(c + 3) * 64 + lr] = v.w * 0.125f;
        }
    }

    float m_i[4], l_i[4], acc[4][4];
    #pragma unroll
    for (int i = 0; i < 4; i++) {
        m_i[i] = -1e30f; l_i[i] = 0.f;
        #pragma unroll
        for (int j = 0; j < 4; j++) acc[i][j] = 0.f;
    }

    for (int kt = 0; kt <= qt; kt++) {
        __syncthreads();
        {
            const float* krow = base + (size_t)(kt * 64 + lr) * (3 * DD) + DD + h * HD + lc;
            #pragma unroll
            for (int m = 0; m < 4; m++) {
                float4 v = *(const float4*)(krow + m * 4);
                int c = lc + m * 4;
                Ks[(c + 0) * 64 + lr] = v.x;
                Ks[(c + 1) * 64 + lr] = v.y;
                Ks[(c + 2) * 64 + lr] = v.z;
                Ks[(c + 3) * 64 + lr] = v.w;
            }
            const float* vrow = base + (size_t)(kt * 64 + lr) * (3 * DD) + 2 * DD + h * HD + lc;
            #pragma unroll
            for (int m = 0; m < 4; m++) {
                *(float4*)&Vs[lr * 64 + lc + m * 4] = *(const float4*)(vrow + m * 4);
            }
        }
        __syncthreads();

        float s[4][4] = {};
        #pragma unroll 4
        for (int k = 0; k < 64; k++) {
            float4 qa = *(const float4*)&Qs[k * 64 + ty * 4];
            float4 kb = *(const float4*)&Ks[k * 64 + tx * 4];
            float ar[4] = {qa.x, qa.y, qa.z, qa.w};
            float br[4] = {kb.x, kb.y, kb.z, kb.w};
            #pragma unroll
            for (int i = 0; i < 4; i++)
                #pragma unroll
                for (int j = 0; j < 4; j++)
                    s[i][j] += ar[i] * br[j];
        }

        if (kt == qt) {
            #pragma unroll
            for (int i = 0; i < 4; i++)
                #pragma unroll
                for (int j = 0; j < 4; j++)
                    if (tx * 4 + j > ty * 4 + i) s[i][j] = -1e30f;
        }

        #pragma unroll
        for (int i = 0; i < 4; i++) {
            float rm = fmaxf(fmaxf(s[i][0], s[i][1]), fmaxf(s[i][2], s[i][3]));
            #pragma unroll
            for (int o = 8; o; o >>= 1) rm = fmaxf(rm, __shfl_xor_sync(0xffffffffu, rm, o));
            float nm = fmaxf(m_i[i], rm);
            float corr = __expf(m_i[i] - nm);
            m_i[i] = nm;
            float rs = 0.f;
            #pragma unroll
            for (int j = 0; j < 4; j++) {
                float p = __expf(s[i][j] - nm);
                Ps[(tx * 4 + j) * PS_STRIDE + ty * 4 + i] = p;
                rs += p;
            }
            #pragma unroll
            for (int o = 8; o; o >>= 1) rs += __shfl_xor_sync(0xffffffffu, rs, o);
            l_i[i] = l_i[i] * corr + rs;
            #pragma unroll
            for (int j = 0; j < 4; j++) acc[i][j] *= corr;
        }
        __syncthreads();

        #pragma unroll 4
        for (int ss = 0; ss < 64; ss++) {
            float4 pa = *(const float4*)&Ps[ss * PS_STRIDE + ty * 4];
            float4 vb = *(const float4*)&Vs[ss * 64 + tx * 4];
            float pr[4] = {pa.x, pa.y, pa.z, pa.w};
            float vr[4] = {vb.x, vb.y, vb.z, vb.w};
            #pragma unroll
            for (int i = 0; i < 4; i++)
                #pragma unroll
                for (int j = 0; j < 4; j++)
                    acc[i][j] += pr[i] * vr[j];
        }
    }

    #pragma unroll
    for (int i = 0; i < 4; i++) {
        float inv = 1.f / l_i[i];
        int t = qt * 64 + ty * 4 + i;
        float4 o;
        o.x = acc[i][0] * inv; o.y = acc[i][1] * inv;
        o.z = acc[i][2] * inv; o.w = acc[i][3] * inv;
        *(float4*)(att + (size_t)(b * TT + t) * DD + h * HD + tx * 4) = o;
    }
}

// ---------------------------------------------------------------------------
// q_scores as GEMM: C[q,t] = (1/16) * queries[q,:].xn[b,t,:]
// Tile 128q x 64t, K = 256, double-buffered, 8x4 per thread.
// Grid: (TT/64, BB)
// ---------------------------------------------------------------------------
__global__ __launch_bounds__(256) void qscore_kernel(
    const float* __restrict__ xn, const float* __restrict__ queries,
    float* __restrict__ qattn) {
    __shared__ float Qs[2][8][128];
    __shared__ float Xs[2][8][64];
    int b  = blockIdx.y;
    int t0 = blockIdx.x * 64;
    int tid = threadIdx.x;
    int tx = tid & 15, ty = tid >> 4;

    int qr = tid >> 1, qc = (tid & 1) * 4;
    int xr = tid >> 1, xc = (tid & 1) * 4;
    bool xact = tid < 128;
    const float* xb = xn + (size_t)b * TT * DD;

    float acc[8][4];
    #pragma unroll
    for (int i = 0; i < 8; i++)
        #pragma unroll
        for (int j = 0; j < 4; j++) acc[i][j] = 0.f;

    {
        float4 qv = *(const float4*)(queries + qr * DD + qc);
        Qs[0][qc + 0][qr] = qv.x; Qs[0][qc + 1][qr] = qv.y;
        Qs[0][qc + 2][qr] = qv.z; Qs[0][qc + 3][qr] = qv.w;
        if (xact) {
            float4 xv = *(const float4*)(xb + (size_t)(t0 + xr) * DD + xc);
            Xs[0][xc + 0][xr] = xv.x; Xs[0][xc + 1][xr] = xv.y;
            Xs[0][xc + 2][xr] = xv.z; Xs[0][xc + 3][xr] = xv.w;
        }
    }
    __syncthreads();

    const int NT = DD >> 3;   // 32
    for (int kt = 0; kt < NT; kt++) {
        int cur = kt & 1;
        float4 qv, xv;
        if (kt + 1 < NT) {
            qv = *(const float4*)(queries + qr * DD + (kt + 1) * 8 + qc);
            if (xact)
                xv = *(const float4*)(xb + (size_t)(t0 + xr) * DD + (kt + 1) * 8 + xc);
        }
        #pragma unroll
        for (int kk = 0; kk < 8; kk++) {
            float a0[8], b0[4];
            *(float4*)&a0[0] = *(const float4*)&Qs[cur][kk][ty * 4];
            *(float4*)&a0[4] = *(const float4*)&Qs[cur][kk][64 + ty * 4];
            *(float4*)&b0[0] = *(const float4*)&Xs[cur][kk][tx * 4];
            #pragma unroll
            for (int i = 0; i < 8; i++)
                #pragma unroll
                for (int j = 0; j < 4; j++)
                    acc[i][j] += a0[i] * b0[j];
        }
        if (kt + 1 < NT) {
            int nxt = cur ^ 1;
            Qs[nxt][qc + 0][qr] = qv.x; Qs[nxt][qc + 1][qr] = qv.y;
            Qs[nxt][qc + 2][qr] = qv.z; Qs[nxt][qc + 3][qr] = qv.w;
            if (xact) {
                Xs[nxt][xc + 0][xr] = xv.x; Xs[nxt][xc + 1][xr] = xv.y;
                Xs[nxt][xc + 2][xr] = xv.z; Xs[nxt][xc + 3][xr] = xv.w;
            }
            __syncthreads();
        }
    }

    #pragma unroll
    for (int i = 0; i < 8; i++) {
        int q = (i < 4) ? ty * 4 + i : 64 + ty * 4 + (i - 4);
        float4 o;
        o.x = acc[i][0] * 0.0625f; o.y = acc[i][1] * 0.0625f;
        o.z = acc[i][2] * 0.0625f; o.w = acc[i][3] * 0.0625f;
        *(float4*)(qattn + (size_t)(b * QQ + q) * TT + t0 + tx * 4) = o;
    }
}

// ---------------------------------------------------------------------------
// Softmax over last dim (2048), in place. One block per row.
// ---------------------------------------------------------------------------
__global__ __launch_bounds__(256) void softmax2048_kernel(float* __restrict__ p) {
    float* row = p + (size_t)blockIdx.x * TT;
    int tid = threadIdx.x;
    float v[8];
    float mx = -1e30f;
    #pragma unroll
    for (int j = 0; j < 8; j++) { v[j] = row[tid + 256 * j]; mx = fmaxf(mx, v[j]); }
    mx = blockReduceMax256(mx);
    float s = 0.f;
    #pragma unroll
    for (int j = 0; j < 8; j++) { v[j] = __expf(v[j] - mx); s += v[j]; }
    s = blockReduceSum256(s);
    float inv = 1.f / s;
    #pragma unroll
    for (int j = 0; j < 8; j++) row[tid + 256 * j] = v[j] * inv;
}

// ---------------------------------------------------------------------------
// selbits: 8 query rows per block share one streaming pass over xn[b].
// Grid: BB*16 blocks.  pairs[b,q] = sigmoid(sum_d sel[q,d]*w[d] + b0)
// ---------------------------------------------------------------------------
__global__ __launch_bounds__(256) void selbits_kernel(
    const float* __restrict__ qattn, const float* __restrict__ xn,
    const float* __restrict__ outp_w, const float* __restrict__ outp_b,
    float* __restrict__ pairs) {
    int b  = blockIdx.x >> 4;
    int qg = blockIdx.x & 15;
    int d  = threadIdx.x;
    __shared__ float ws[8][64];
    float acc[8] = {};
    const float* xb = xn + (size_t)b * TT * DD;
    int g  = threadIdx.x >> 5;
    int tt = threadIdx.x & 31;
    const float* wbase = qattn + (size_t)(b * QQ + qg * 8 + g) * TT;

    for (int t0 = 0; t0 < TT; t0 += 64) {
        ws[g][tt]      = wbase[t0 + tt];
        ws[g][tt + 32] = wbase[t0 + tt + 32];
        __syncthreads();
        #pragma unroll 8
        for (int t = 0; t < 64; t++) {
            float x = xb[(size_t)(t0 + t) * DD + d];
            #pragma unroll
            for (int g2 = 0; g2 < 8; g2++) acc[g2] += ws[g2][t] * x;
        }
        __syncthreads();
    }

    float wd = outp_w[d];
    #pragma unroll
    for (int g2 = 0; g2 < 8; g2++) {
        float s = blockReduceSum256(acc[g2] * wd);
        if (d == 0)
            pairs[b * QQ + qg * 8 + g2] =
                1.f / (1.f + __expf(-(s + outp_b[0])));
    }
}

// ---------------------------------------------------------------------------
// 64-step recurrent MLP scan. One block per batch row, 64 threads.
// ---------------------------------------------------------------------------
__global__ __launch_bounds__(64) void scan_kernel(
    const float* __restrict__ pairs,
    const float* __restrict__ w1, const float* __restrict__ b1,
    const float* __restrict__ w2, const float* __restrict__ b2,
    const float* __restrict__ w3, const float* __restrict__ b3,
    float* __restrict__ sum_all) {
    int b = blockIdx.x;
    int j = threadIdx.x;
    __shared__ float h1[64], h2[64];
    __shared__ float carry;
    if (j == 0) carry = 0.f;

    float w1a = w1[j], w1b = w1[64 + j], w1c = w1[128 + j], bb1 = b1[j];
    float w2c[64];
    #pragma unroll
    for (int k = 0; k < 64; k++) w2c[k] = w2[k * 64 + j];
    float bb2 = b2[j];
    __syncthreads();

    for (int i = 0; i < 64; i++) {
        float z0 = pairs[b * QQ + i * 2];
        float z1 = pairs[b * QQ + i * 2 + 1];
        float z2 = carry;
        h1[j] = fmaxf(0.f, z0 * w1a + z1 * w1b + z2 * w1c + bb1);
        __syncthreads();
        float acc = bb2;
        #pragma unroll
        for (int k = 0; k < 64; k++) acc += h1[k] * w2c[k];
        h2[j] = fmaxf(0.f, acc);
        __syncthreads();
        if (j == 0) {
            float o0 = b3[0], o1 = b3[1];
            #pragma unroll
            for (int k = 0; k < 64; k++) {
                o0 += h2[k] * w3[k * 2];
                o1 += h2[k] * w3[k * 2 + 1];
            }
            o0 = 1.f / (1.f + __expf(-o0));
            o1 = 1.f / (1.f + __expf(-o1));
            sum_all[b * 65 + i] = o0;
            carry = o1;
        }
        __syncthreads();
    }
    if (j == 0) sum_all[b * 65 + 64] = carry;
}

// ---------------------------------------------------------------------------
// Launch
// ---------------------------------------------------------------------------
extern "C" void kernel_launch(void* const* d_in, const int* in_sizes, int n_in,
                              void* d_out, int out_size) {
    const int*   tokens   = (const int*)  d_in[0];
    const float* embed    = (const float*)d_in[1];
    const float* ln1_w    = (const float*)d_in[2];
    const float* ln1_b    = (const float*)d_in[3];
    const float* qkv_w    = (const float*)d_in[4];
    const float* qkv_b    = (const float*)d_in[5];
    const float* proj_w   = (const float*)d_in[6];
    const float* proj_b   = (const float*)d_in[7];
    const float* ln2_w    = (const float*)d_in[8];
    const float* ln2_b    = (const float*)d_in[9];
    const float* ffn1_w   = (const float*)d_in[10];
    const float* ffn1_b   = (const float*)d_in[11];
    const float* ffn2_w   = (const float*)d_in[12];
    const float* ffn2_b   = (const float*)d_in[13];
    const float* lnf_w    = (const float*)d_in[14];
    const float* lnf_b    = (const float*)d_in[15];
    const float* queries  = (const float*)d_in[16];
    const float* outp_w   = (const float*)d_in[17];
    const float* outp_b   = (const float*)d_in[18];
    const float* mlp_w1   = (const float*)d_in[19];
    const float* mlp_b1   = (const float*)d_in[20];
    const float* mlp_w2   = (const float*)d_in[21];
    const float* mlp_b2   = (const float*)d_in[22];
    const float* mlp_w3   = (const float*)d_in[23];
    const float* mlp_b3   = (const float*)d_in[24];

    float* out     = (float*)d_out;
    float* sum_all = out;                  // (B,65)   = 260
    float* pairs   = out + 260;            // (B,64,2) = 512
    float* qattn   = out + 772;            // (B,128,2048)

    float *px, *pxn, *pqkv, *patt, *ph;
    cudaGetSymbolAddress((void**)&px,   g_x);
    cudaGetSymbolAddress((void**)&pxn,  g_xn);
    cudaGetSymbolAddress((void**)&pqkv, g_qkv);
    cudaGetSymbolAddress((void**)&patt, g_att);
    cudaGetSymbolAddress((void**)&ph,   g_h);

    cudaFuncSetAttribute(fattn_kernel,
                         cudaFuncAttributeMaxDynamicSharedMemorySize, FATTN_SMEM);

    const int ROWS = BB * TT;  // 8192

    embed_kernel<<<ROWS, 256>>>(tokens, embed, px);

    for (int l = 0; l < LL; l++) {
        ln_kernel<<<ROWS, 256>>>(px, ln1_w + l * DD, ln1_b + l * DD, pxn);
        gemm128_kernel<128, 0><<<dim3(6, ROWS / 128), 256>>>(
            pxn, qkv_w + (size_t)l * DD * 3 * DD, qkv_b + l * 3 * DD, pqkv,
            ROWS, 3 * DD, DD);
        rope_kernel<<<ROWS, 256>>>(pqkv);
        fattn_kernel<<<dim3(TT / 64, HH, BB), 256, FATTN_SMEM>>>(pqkv, patt);
        gemm128_kernel<64, 2><<<dim3(4, ROWS / 128), 256>>>(
            patt, proj_w + (size_t)l * DD * DD, proj_b + l * DD, px,
            ROWS, DD, DD);
        ln_kernel<<<ROWS, 256>>>(px, ln2_w + l * DD, ln2_b + l * DD, pxn);
        gemm128_kernel<128, 1><<<dim3(8, ROWS / 128), 256>>>(
            pxn, ffn1_w + (size_t)l * DD * 4 * DD, ffn1_b + l * 4 * DD, ph,
            ROWS, 4 * DD, DD);
        gemm128_kernel<64, 2><<<dim3(4, ROWS / 128), 256>>>(
            ph, ffn2_w + (size_t)l * 4 * DD * DD, ffn2_b + l * DD, px,
            ROWS, DD, 4 * DD);
    }

    ln_kernel<<<ROWS, 256>>>(px, lnf_w, lnf_b, pxn);
    qscore_kernel<<<dim3(TT / 64, BB), 256>>>(pxn, queries, qattn);
    softmax2048_kernel<<<BB * QQ, 256>>>(qattn);
    selbits_kernel<<<BB * 16, 256>>>(qattn, pxn, outp_w, outp_b, pairs);
    scan_kernel<<<BB, 64>>>(pairs, mlp_w1, mlp_b1, mlp_w2, mlp_b2,
                            mlp_w3, mlp_b3, sum_all);
}